// round 1
// baseline (speedup 1.0000x reference)
#include <cuda_runtime.h>
#include <cuda_bf16.h>
#include <cstdint>

// Problem constants
#define BH   32          // B*H heads
#define NN   2048        // query rows
#define TT   2048        // key rows
#define DD   128         // head dim
#define RR   64          // JL rank
#define KC   192         // concatenated K = DD + RR

// Packed operand scratch (device globals; allocation-free rule)
__device__ float g_A [BH * (size_t)NN * KC];   // [h][n][192]  = [q | q@G / R]
__device__ float g_Bm[BH * (size_t)TT * KC];   // [h][t][192]  = [k_quant | sign(e@G)]

// ---------------------------------------------------------------------------
// Prep kernel: build Bm rows. 2 rows per block, 128 threads.
//   thread = (local_row lr in {0,1}) x (rank index r in 0..63)
// ---------------------------------------------------------------------------
__global__ void prep_b_kernel(const float* __restrict__ k_orig,
                              const float* __restrict__ k_quant,
                              const float* __restrict__ G) {
    const int row0 = blockIdx.x * 2;          // global row = h*TT + t
    const int lr   = threadIdx.x >> 6;        // 0..1
    const int r    = threadIdx.x & 63;        // 0..63

    __shared__ float es[2][DD];

    const float* ko = k_orig  + (size_t)row0 * DD;
    const float* kq = k_quant + (size_t)row0 * DD;
    float* dstB = g_Bm + (size_t)row0 * KC;

    // load residual e = k_orig - k_quant for both rows; also pass through k_quant
    for (int i = threadIdx.x; i < 2 * DD; i += 128) {
        float kqv = kq[i];
        es[i >> 7][i & 127] = ko[i] - kqv;
        dstB[(i >> 7) * KC + (i & 127)] = kqv;
    }
    __syncthreads();

    float acc = 0.f;
#pragma unroll 8
    for (int d = 0; d < DD; d++)
        acc = fmaf(es[lr][d], G[d * RR + r], acc);

    float s = (acc > 0.f) ? 1.f : ((acc < 0.f) ? -1.f : 0.f);
    g_Bm[(size_t)(row0 + lr) * KC + DD + r] = s;
}

// ---------------------------------------------------------------------------
// Prep kernel: build A rows. [q | (q@G)/R]
// ---------------------------------------------------------------------------
__global__ void prep_a_kernel(const float* __restrict__ q,
                              const float* __restrict__ G) {
    const int row0 = blockIdx.x * 2;          // global row = h*NN + n
    const int lr   = threadIdx.x >> 6;
    const int r    = threadIdx.x & 63;

    __shared__ float qs[2][DD];

    const float* qr = q + (size_t)row0 * DD;
    float* dstA = g_A + (size_t)row0 * KC;

    for (int i = threadIdx.x; i < 2 * DD; i += 128) {
        float v = qr[i];
        qs[i >> 7][i & 127] = v;
        dstA[(i >> 7) * KC + (i & 127)] = v;
    }
    __syncthreads();

    float acc = 0.f;
#pragma unroll 8
    for (int d = 0; d < DD; d++)
        acc = fmaf(qs[lr][d], G[d * RR + r], acc);

    g_A[(size_t)(row0 + lr) * KC + DD + r] = acc * (1.0f / (float)RR);
}

// ---------------------------------------------------------------------------
// Main batched GEMM: out[h] = A[h] (2048x192) @ Bm[h]^T (2048x192)
// 128x128 CTA tile, BK=16, 256 threads, 8x8 per-thread micro-tile in split
// quadrants (cols {tx*4..+3, 64+tx*4..+3}) for conflict-free LDS.128.
// ---------------------------------------------------------------------------
#define BK 16
#define SMPAD 132   // 128 + 4 padding

__global__ __launch_bounds__(256, 2)
void gemm_kernel(float* __restrict__ out) {
    const int h = blockIdx.z;
    const float* Ab = g_A  + (size_t)h * NN * KC + (size_t)blockIdx.y * 128 * KC;
    const float* Bb = g_Bm + (size_t)h * TT * KC + (size_t)blockIdx.x * 128 * KC;
    float* C = out + (size_t)h * NN * TT + (size_t)blockIdx.y * 128 * TT
                   + (size_t)blockIdx.x * 128;

    __shared__ float As[BK][SMPAD];
    __shared__ float Bs[BK][SMPAD];

    const int tid = threadIdx.x;
    const int tx = tid & 15;     // 0..15  -> columns
    const int ty = tid >> 4;     // 0..15  -> rows

    const int lrow = tid >> 2;         // 0..63
    const int lcol = (tid & 3) * 4;    // 0,4,8,12

    float acc[8][8];
#pragma unroll
    for (int i = 0; i < 8; i++)
#pragma unroll
        for (int j = 0; j < 8; j++) acc[i][j] = 0.f;

    float ar[8], br[8];

    for (int k0 = 0; k0 < KC; k0 += BK) {
        // cooperative load: transpose into smem [k][row]
#pragma unroll
        for (int i = 0; i < 2; i++) {
            const int r = lrow + i * 64;
            float4 va = *(const float4*)(Ab + (size_t)r * KC + k0 + lcol);
            As[lcol + 0][r] = va.x; As[lcol + 1][r] = va.y;
            As[lcol + 2][r] = va.z; As[lcol + 3][r] = va.w;
            float4 vb = *(const float4*)(Bb + (size_t)r * KC + k0 + lcol);
            Bs[lcol + 0][r] = vb.x; Bs[lcol + 1][r] = vb.y;
            Bs[lcol + 2][r] = vb.z; Bs[lcol + 3][r] = vb.w;
        }
        __syncthreads();

#pragma unroll
        for (int kk = 0; kk < BK; kk++) {
            *(float4*)&ar[0] = *(const float4*)&As[kk][ty * 4];
            *(float4*)&ar[4] = *(const float4*)&As[kk][64 + ty * 4];
            *(float4*)&br[0] = *(const float4*)&Bs[kk][tx * 4];
            *(float4*)&br[4] = *(const float4*)&Bs[kk][64 + tx * 4];
#pragma unroll
            for (int i = 0; i < 8; i++)
#pragma unroll
                for (int j = 0; j < 8; j++)
                    acc[i][j] = fmaf(ar[i], br[j], acc[i][j]);
        }
        __syncthreads();
    }

    // epilogue: rows {ty*4+i, 64+ty*4+i}, cols {tx*4+j, 64+tx*4+j}
#pragma unroll
    for (int i = 0; i < 8; i++) {
        const int rr = (i < 4) ? (ty * 4 + i) : (64 + ty * 4 + (i - 4));
        float* crow = C + (size_t)rr * TT;
        *(float4*)(crow + tx * 4)      = make_float4(acc[i][0], acc[i][1], acc[i][2], acc[i][3]);
        *(float4*)(crow + 64 + tx * 4) = make_float4(acc[i][4], acc[i][5], acc[i][6], acc[i][7]);
    }
}

// ---------------------------------------------------------------------------
extern "C" void kernel_launch(void* const* d_in, const int* in_sizes, int n_in,
                              void* d_out, int out_size) {
    const float* q      = (const float*)d_in[0];
    const float* k_orig = (const float*)d_in[1];
    const float* k_quant= (const float*)d_in[2];
    const float* G      = (const float*)d_in[3];
    float* out = (float*)d_out;

    // Build packed operands
    prep_b_kernel<<<BH * TT / 2, 128>>>(k_orig, k_quant, G);
    prep_a_kernel<<<BH * NN / 2, 128>>>(q, G);

    // Batched GEMM over heads
    dim3 grid(TT / 128, NN / 128, BH);
    gemm_kernel<<<grid, 256>>>(out);
}

// round 4
// speedup vs baseline: 3.4167x; 3.4167x over previous
#include <cuda_runtime.h>
#include <cuda_bf16.h>
#include <cstdint>

// ---------------------------------------------------------------- constants
#define BH        32
#define NROW      2048
#define TROW      2048
#define ROWS      (BH * 2048)        // 65536 rows per side
#define NBLK128   (ROWS / 128)       // 512 blocks of 128 rows
#define ABLOCK    81920              // 64KB tf32 frags + 16KB bf16 frags
#define BF16_OFF  65536

// Packed operand buffers in MMA-fragment order (~40MB each)
__device__ __align__(128) unsigned char g_Apk[(size_t)NBLK128 * ABLOCK];
__device__ __align__(128) unsigned char g_Bpk[(size_t)NBLK128 * ABLOCK];

// ---------------------------------------------------------------- helpers
__device__ __forceinline__ uint32_t smem_u32(const void* p) {
    uint32_t a;
    asm("{ .reg .u64 t; cvta.to.shared.u64 t, %1; cvt.u32.u64 %0, t; }" : "=r"(a) : "l"(p));
    return a;
}
__device__ __forceinline__ uint32_t f2tf32(float v) {
    uint32_t o;
    asm("cvt.rna.tf32.f32 %0, %1;" : "=r"(o) : "f"(v));
    return o;
}
__device__ __forceinline__ uint32_t pack_bf16x2(float lo, float hi) {
    uint32_t o;   // first PTX source -> upper half
    asm("cvt.rn.bf16x2.f32 %0, %1, %2;" : "=r"(o) : "f"(hi), "f"(lo));
    return o;
}
__device__ __forceinline__ void cp_async16(uint32_t saddr, const void* gptr) {
    asm volatile("cp.async.cg.shared.global [%0], [%1], 16;"
                 :: "r"(saddr), "l"(__cvta_generic_to_global(gptr)) : "memory");
}
__device__ __forceinline__ float signf(float v) {
    return (v > 0.f) ? 1.f : ((v < 0.f) ? -1.f : 0.f);
}

// ---------------------------------------------------------------- prep kernel
// One CTA = 64 rows. side 0 -> A operands (from q), side 1 -> B (from ko,kq).
__global__ void __launch_bounds__(256) prep_kernel(const float* __restrict__ q,
                                                   const float* __restrict__ ko,
                                                   const float* __restrict__ kq,
                                                   const float* __restrict__ G) {
    extern __shared__ float sm[];
    float* Rows = sm;            // [64][128]
    float* E    = sm + 8192;     // [64][128]
    float* Gs   = sm + 16384;    // [128][64]
    float* P    = sm + 24576;    // [64][64]

    const int tid  = threadIdx.x;
    const int side = blockIdx.y;
    const int blk64  = blockIdx.x;
    const size_t row0 = (size_t)blk64 * 64;
    const int blk128 = blk64 >> 1;
    const int half   = blk64 & 1;

    {
        float4* d = (float4*)Gs; const float4* s = (const float4*)G;
        for (int i = tid; i < 2048; i += 256) d[i] = s[i];
    }
    {
        float4* R4 = (float4*)Rows;
        const size_t b4 = row0 * 32;
        if (side == 0) {
            const float4* s = (const float4*)q;
            for (int i = tid; i < 2048; i += 256) R4[i] = s[b4 + i];
        } else {
            const float4* sk = (const float4*)kq;
            const float4* so = (const float4*)ko;
            float4* E4 = (float4*)E;
            for (int i = tid; i < 2048; i += 256) {
                float4 a = so[b4 + i], b = sk[b4 + i];
                R4[i] = b;
                E4[i] = make_float4(a.x - b.x, a.y - b.y, a.z - b.z, a.w - b.w);
            }
        }
    }
    __syncthreads();

    // projection: 4 rows x 4 ranks per thread (fp32 exact)
    {
        const float* src = side ? E : Rows;
        const int rq = (tid & 15) * 4;
        const int mq = (tid >> 4) * 4;
        float acc[4][4];
#pragma unroll
        for (int i = 0; i < 4; i++)
#pragma unroll
            for (int j = 0; j < 4; j++) acc[i][j] = 0.f;
#pragma unroll 8
        for (int k = 0; k < 128; k++) {
            float4 g = *(const float4*)&Gs[k * 64 + rq];
            float e0 = src[(mq + 0) * 128 + k];
            float e1 = src[(mq + 1) * 128 + k];
            float e2 = src[(mq + 2) * 128 + k];
            float e3 = src[(mq + 3) * 128 + k];
            acc[0][0] = fmaf(e0, g.x, acc[0][0]); acc[0][1] = fmaf(e0, g.y, acc[0][1]);
            acc[0][2] = fmaf(e0, g.z, acc[0][2]); acc[0][3] = fmaf(e0, g.w, acc[0][3]);
            acc[1][0] = fmaf(e1, g.x, acc[1][0]); acc[1][1] = fmaf(e1, g.y, acc[1][1]);
            acc[1][2] = fmaf(e1, g.z, acc[1][2]); acc[1][3] = fmaf(e1, g.w, acc[1][3]);
            acc[2][0] = fmaf(e2, g.x, acc[2][0]); acc[2][1] = fmaf(e2, g.y, acc[2][1]);
            acc[2][2] = fmaf(e2, g.z, acc[2][2]); acc[2][3] = fmaf(e2, g.w, acc[2][3]);
            acc[3][0] = fmaf(e3, g.x, acc[3][0]); acc[3][1] = fmaf(e3, g.y, acc[3][1]);
            acc[3][2] = fmaf(e3, g.z, acc[3][2]); acc[3][3] = fmaf(e3, g.w, acc[3][3]);
        }
#pragma unroll
        for (int i = 0; i < 4; i++)
#pragma unroll
            for (int j = 0; j < 4; j++) {
                float v = acc[i][j];
                P[(mq + i) * 64 + rq + j] = side ? signf(v) : v * (1.0f / 64.0f);
            }
    }
    __syncthreads();

    const int lane = tid & 31;
    const int g  = lane >> 2;
    const int tg = lane & 3;

    if (side == 0) {
        unsigned char* Ab = g_Apk + (size_t)blk128 * ABLOCK;
        const int mf0 = half * 4;
        // tf32 A frags: 16 kf x 4 local m-tiles
        for (int fi = tid >> 5; fi < 64; fi += 8) {
            const int kf = fi >> 2, mfl = fi & 3;
            const int r0 = mfl * 16 + g;
            const int k0 = kf * 8 + tg;
            uint4 v;
            v.x = f2tf32(Rows[(r0)     * 128 + k0]);
            v.y = f2tf32(Rows[(r0 + 8) * 128 + k0]);
            v.z = f2tf32(Rows[(r0)     * 128 + k0 + 4]);
            v.w = f2tf32(Rows[(r0 + 8) * 128 + k0 + 4]);
            *(uint4*)(Ab + (size_t)((kf * 8 + mf0 + mfl) * 512 + lane * 16)) = v;
        }
        // bf16 A frags (P): 4 kf x 4 local m-tiles
        for (int fi = tid >> 5; fi < 16; fi += 8) {
            const int kf = fi >> 2, mfl = fi & 3;
            const int r0 = mfl * 16 + g;
            uint4 v;
            uint32_t* vv = (uint32_t*)&v;
#pragma unroll
            for (int j = 0; j < 4; j++) {
                const int r = r0 + 8 * (j & 1);
                const int kb = kf * 16 + 2 * tg + 8 * (j >> 1);
                vv[j] = pack_bf16x2(P[r * 64 + kb], P[r * 64 + kb + 1]);
            }
            *(uint4*)(Ab + (size_t)(BF16_OFF + (kf * 8 + mf0 + mfl) * 512 + lane * 16)) = v;
        }
    } else {
        unsigned char* Bb = g_Bpk + (size_t)blk128 * ABLOCK;
        const int nf0 = half * 8;
        // tf32 B frags: 16 kf x 8 local n-tiles
        for (int fi = tid >> 5; fi < 128; fi += 8) {
            const int kf = fi >> 3, nfl = fi & 7;
            const int n = nfl * 8 + g;
            uint2 v;
            v.x = f2tf32(Rows[n * 128 + kf * 8 + tg]);
            v.y = f2tf32(Rows[n * 128 + kf * 8 + tg + 4]);
            *(uint2*)(Bb + (size_t)((kf * 16 + nf0 + nfl) * 256 + lane * 8)) = v;
        }
        // bf16 B frags (S): 4 kf x 8 local n-tiles
        for (int fi = tid >> 5; fi < 32; fi += 8) {
            const int kf = fi >> 3, nfl = fi & 7;
            const int n = nfl * 8 + g;
            uint2 v;
            const int kb0 = kf * 16 + 2 * tg;
            v.x = pack_bf16x2(P[n * 64 + kb0],     P[n * 64 + kb0 + 1]);
            v.y = pack_bf16x2(P[n * 64 + kb0 + 8], P[n * 64 + kb0 + 9]);
            *(uint2*)(Bb + (size_t)(BF16_OFF + (kf * 16 + nf0 + nfl) * 256 + lane * 8)) = v;
        }
    }
}

// ---------------------------------------------------------------- GEMM
// 128x128 tile, 8 warps (4m x 2n), 5 K-stages of 32KB via cp.async ring of 3.
// ALL smem loads / MMAs are volatile asm with memory clobbers: they must not
// move across cp.async.wait_group / __syncthreads, nor CSE across ring-slot
// reuse (slot s%3 repeats at s and s+3).
#define STAGE_BYTES 32768
#define SMEM_GEMM   (3 * STAGE_BYTES)

template <bool TF32>
__device__ __forceinline__ void compute_stage(uint32_t sA, uint32_t sB,
                                              int mw, int nw, int lane,
                                              float acc[2][8][4]) {
#pragma unroll
    for (int kf = 0; kf < 4; kf++) {
        uint32_t b[8][2];
#pragma unroll
        for (int j = 0; j < 8; j++) {
            uint32_t addr = sB + ((kf * 16 + nw * 8 + j) * 32 + lane) * 8;
            asm volatile("ld.shared.v2.u32 {%0,%1}, [%2];"
                : "=r"(b[j][0]), "=r"(b[j][1]) : "r"(addr) : "memory");
        }
#pragma unroll
        for (int i = 0; i < 2; i++) {
            uint32_t a[4];
            uint32_t addr = sA + ((kf * 8 + mw * 2 + i) * 32 + lane) * 16;
            asm volatile("ld.shared.v4.u32 {%0,%1,%2,%3}, [%4];"
                : "=r"(a[0]), "=r"(a[1]), "=r"(a[2]), "=r"(a[3]) : "r"(addr) : "memory");
#pragma unroll
            for (int j = 0; j < 8; j++) {
                if (TF32)
                    asm volatile("mma.sync.aligned.m16n8k8.row.col.f32.tf32.tf32.f32 "
                        "{%0,%1,%2,%3}, {%4,%5,%6,%7}, {%8,%9}, {%0,%1,%2,%3};"
                        : "+f"(acc[i][j][0]), "+f"(acc[i][j][1]),
                          "+f"(acc[i][j][2]), "+f"(acc[i][j][3])
                        : "r"(a[0]), "r"(a[1]), "r"(a[2]), "r"(a[3]),
                          "r"(b[j][0]), "r"(b[j][1]));
                else
                    asm volatile("mma.sync.aligned.m16n8k16.row.col.f32.bf16.bf16.f32 "
                        "{%0,%1,%2,%3}, {%4,%5,%6,%7}, {%8,%9}, {%0,%1,%2,%3};"
                        : "+f"(acc[i][j][0]), "+f"(acc[i][j][1]),
                          "+f"(acc[i][j][2]), "+f"(acc[i][j][3])
                        : "r"(a[0]), "r"(a[1]), "r"(a[2]), "r"(a[3]),
                          "r"(b[j][0]), "r"(b[j][1]));
            }
        }
    }
}

__global__ void __launch_bounds__(256, 2) gemm_kernel(float* __restrict__ out) {
    extern __shared__ char smem[];
    const uint32_t sb = smem_u32(smem);
    const int tid  = threadIdx.x;
    const int lane = tid & 31;
    const int w    = tid >> 5;
    const int mw   = w & 3;
    const int nw   = w >> 2;

    const int bx = blockIdx.x, by = blockIdx.y, h = blockIdx.z;
    const unsigned char* Ab = g_Apk + (size_t)(h * 16 + by) * ABLOCK;
    const unsigned char* Bb = g_Bpk + (size_t)(h * 16 + bx) * ABLOCK;

    auto prefetch = [&](int s) {
        const int sl = s % 3;
        const size_t goff = (s < 4) ? (size_t)s * 16384 : (size_t)BF16_OFF;
        const uint32_t dA = sb + sl * STAGE_BYTES;
        const uint32_t dB = dA + 16384;
#pragma unroll
        for (int i = 0; i < 4; i++) {
            const int off = (tid + i * 256) * 16;
            cp_async16(dA + off, Ab + goff + off);
            cp_async16(dB + off, Bb + goff + off);
        }
        asm volatile("cp.async.commit_group;" ::: "memory");
    };

    float acc[2][8][4];
#pragma unroll
    for (int i = 0; i < 2; i++)
#pragma unroll
        for (int j = 0; j < 8; j++)
#pragma unroll
            for (int c = 0; c < 4; c++) acc[i][j][c] = 0.f;

    prefetch(0);
    prefetch(1);

#pragma unroll
    for (int s = 0; s < 5; s++) {
        if (s == 4) asm volatile("cp.async.wait_group 0;" ::: "memory");
        else        asm volatile("cp.async.wait_group 1;" ::: "memory");
        __syncthreads();
        const int sl = s % 3;
        const uint32_t sA = sb + sl * STAGE_BYTES;
        const uint32_t sB = sA + 16384;
        if (s < 4) compute_stage<true >(sA, sB, mw, nw, lane, acc);
        else       compute_stage<false>(sA, sB, mw, nw, lane, acc);
        __syncthreads();
        if (s + 2 < 5) prefetch(s + 2);
    }

    // epilogue: STG.64, full coalesced rows
    const int g = lane >> 2, tg = lane & 3;
    const size_t rowbase = (size_t)h * 2048;
#pragma unroll
    for (int i = 0; i < 2; i++) {
        const int m = by * 128 + mw * 32 + i * 16 + g;
        float* r0 = out + (rowbase + m)     * 2048 + bx * 128 + nw * 64;
        float* r1 = out + (rowbase + m + 8) * 2048 + bx * 128 + nw * 64;
#pragma unroll
        for (int j = 0; j < 8; j++) {
            *(float2*)(r0 + j * 8 + tg * 2) = make_float2(acc[i][j][0], acc[i][j][1]);
            *(float2*)(r1 + j * 8 + tg * 2) = make_float2(acc[i][j][2], acc[i][j][3]);
        }
    }
}

// ---------------------------------------------------------------- launch
extern "C" void kernel_launch(void* const* d_in, const int* in_sizes, int n_in,
                              void* d_out, int out_size) {
    const float* q  = (const float*)d_in[0];
    const float* ko = (const float*)d_in[1];
    const float* kq = (const float*)d_in[2];
    const float* G  = (const float*)d_in[3];
    float* out = (float*)d_out;

    cudaFuncSetAttribute(prep_kernel, cudaFuncAttributeMaxDynamicSharedMemorySize, 114688);
    cudaFuncSetAttribute(gemm_kernel, cudaFuncAttributeMaxDynamicSharedMemorySize, SMEM_GEMM);

    prep_kernel<<<dim3(ROWS / 64, 2), 256, 114688>>>(q, ko, kq, G);

    dim3 grid(TROW / 128, NROW / 128, BH);
    gemm_kernel<<<grid, 256, SMEM_GEMM>>>(out);
}